// round 7
// baseline (speedup 1.0000x reference)
#include <cuda_runtime.h>
#include <stdint.h>
#include <math.h>

// HighPassFilter: order-2 IIR biquad, 256 sequences of T=65536 float32.
// R7: R5's working cp.async double-buffered pipeline, occupancy doubled:
// CHUNK 256->128 with WARM kept at the VALIDATED 96 samples (truncation error
// depends only on WARM; 5.6e-7 measured). 16 warps/seq -> 4096 warps
// (~27/SM vs 13.8), covering the DRAM latency the R5 profile showed exposed
// (occ 18%, issue 24.6%, DRAM 56%). Warm-up read amplification (1.75x) is
// absorbed by L2 (neighbor warp streams the same region).

#define T_LEN   65536
#define CHUNK   128     // samples per lane
#define WARM    96      // warm-up samples (validated; do not reduce)
#define JT      32      // j-tile width
#define NT      ((CHUNK + WARM) / JT)   // 7 tiles per warp
#define BLOCK_WARPS 2
#define ROWSTRIDE 36    // 32 + 4 pad; 16B accesses at 144B stride: conflict-free

#define ROWBYTES  (ROWSTRIDE * 4)       // 144
#define BUFBYTES  (32 * ROWBYTES)       // 4608

__device__ __forceinline__ void cp_async16(uint32_t dst_smem, const float* src, int src_size)
{
    asm volatile("cp.async.cg.shared.global [%0], [%1], 16, %2;\n"
                 :: "r"(dst_smem), "l"(src), "r"(src_size));
}

__global__ __launch_bounds__(BLOCK_WARPS * 32, 1)
void biquad_hp_kernel(const float* __restrict__ x, float* __restrict__ y,
                      float b0, float b1, float b2, float na1, float na2)
{
    // double-buffered transpose tiles per warp
    __shared__ __align__(16) float tile[BLOCK_WARPS][2][32][ROWSTRIDE];

    const int w    = threadIdx.x >> 5;
    const int lane = threadIdx.x & 31;
    const int g    = lane >> 3;   // chunk subgroup (0..3)
    const int m    = lane & 7;    // float4 slot within 32-sample tile (0..7)

    // 16 warps per sequence, each warp owns 32 contiguous chunks = 4096 samples
    const int gw   = blockIdx.x * BLOCK_WARPS + w;
    const int seq  = gw >> 4;
    const int wseq = gw & 15;

    const long long seqbase = (long long)seq * T_LEN;
    const float* xs = x + seqbase;
    float*       ys = y + seqbase;
    const int warpbase = wseq * (32 * CHUNK);
    const int slotbase = warpbase + g * CHUNK + 4 * m;

    // SMEM byte addresses of this lane's two cp.async destination sets.
    // it-step "it" targets row c = it*4+g, float offset 4m:
    //   byte = it*(4*ROWBYTES) + g*ROWBYTES + 16*m
    uint32_t smem_dst[2];
    {
        uint32_t base;
        asm("{ .reg .u64 t; cvta.to.shared.u64 t, %1; cvt.u32.u64 %0, t; }"
            : "=r"(base) : "l"(&tile[w][0][0][0]));
        const uint32_t off = (uint32_t)g * ROWBYTES + (uint32_t)m * 16;
        smem_dst[0] = base + off;
        smem_dst[1] = base + BUFBYTES + off;
    }
    const uint32_t rowstep = 4 * ROWBYTES;   // 576 bytes per it-step

    float xm1 = 0.f, xm2 = 0.f, ym1 = 0.f, ym2 = 0.f;

    // ---- prologue: prefetch tile 0 (jt = -WARM) into buffer 0
    {
        const int jt = -WARM;
        #pragma unroll
        for (int it = 0; it < 8; ++it) {
            int p = slotbase + it * (4 * CHUNK) + jt;
            cp_async16(smem_dst[0] + it * rowstep,
                       xs + (p >= 0 ? p : 0), p >= 0 ? 16 : 0);
        }
        asm volatile("cp.async.commit_group;\n");
    }

    #pragma unroll
    for (int t = 0; t < NT; ++t) {
        const int  jt   = -WARM + t * JT;
        const bool emit = (jt >= 0);
        float (*buf)[ROWSTRIDE] = tile[w][t & 1];
        float* row = buf[lane];

        // ---- issue next tile's cp.async into the other buffer
        if (t + 1 < NT) {
            const int jn = jt + JT;
            #pragma unroll
            for (int it = 0; it < 8; ++it) {
                int p = slotbase + it * (4 * CHUNK) + jn;
                cp_async16(smem_dst[(t + 1) & 1] + it * rowstep,
                           xs + (p >= 0 ? p : 0), p >= 0 ? 16 : 0);
            }
            asm volatile("cp.async.commit_group;\n");
            asm volatile("cp.async.wait_group 1;\n");   // tile t complete
        } else {
            asm volatile("cp.async.wait_group 0;\n");
        }
        __syncwarp();

        // ---- advance this lane's chunk 32 samples (serial IIR chain)
        #pragma unroll
        for (int jj = 0; jj < JT; jj += 4) {
            float4 xv = *reinterpret_cast<float4*>(&row[jj]);

            float t0 = fmaf(b2, xm2, fmaf(b1, xm1, b0 * xv.x));
            float y0 = fmaf(na2, ym2, fmaf(na1, ym1, t0));
            float t1 = fmaf(b2, xm1, fmaf(b1, xv.x, b0 * xv.y));
            float y1 = fmaf(na2, ym1, fmaf(na1, y0, t1));
            float t2 = fmaf(b2, xv.x, fmaf(b1, xv.y, b0 * xv.z));
            float y2 = fmaf(na2, y0, fmaf(na1, y1, t2));
            float t3 = fmaf(b2, xv.y, fmaf(b1, xv.z, b0 * xv.w));
            float y3 = fmaf(na2, y1, fmaf(na1, y2, t3));

            xm2 = xv.z; xm1 = xv.w;
            ym2 = y2;   ym1 = y3;

            if (emit)
                *reinterpret_cast<float4*>(&row[jj]) =
                    make_float4(y0, y1, y2, y3);
        }
        __syncwarp();

        // ---- coalesced store of computed tile (in-place transposed SMEM)
        if (emit) {
            #pragma unroll
            for (int it = 0; it < 8; ++it) {
                int c = it * 4 + g;
                int p = slotbase + it * (4 * CHUNK) + jt;
                *reinterpret_cast<float4*>(ys + p) =
                    *reinterpret_cast<const float4*>(&buf[c][4 * m]);
            }
        }
        __syncwarp();
    }
}

extern "C" void kernel_launch(void* const* d_in, const int* in_sizes, int n_in,
                              void* d_out, int out_size)
{
    const float* x = (const float*)d_in[0];
    float*       y = (float*)d_out;

    const int total = in_sizes[0];
    const int nseq  = total / T_LEN;          // 256 for the given shapes

    const double w0    = 2.0 * M_PI * (700.0 / 16000.0);
    const double cw    = cos(w0);
    const double sw    = sin(w0);
    const double q     = 0.70710678;
    const double alpha = sw / (2.0 * q);
    const double a0    = 1.0 + alpha;

    const float b0 = (float)(((1.0 + cw) / 2.0) / a0);
    const float b1 = (float)((-(1.0 + cw)) / a0);
    const float b2 = b0;
    const float a1 = (float)((-2.0 * cw) / a0);
    const float a2 = (float)((1.0 - alpha) / a0);

    const int warps_total = nseq * 16;                 // 16 warps per sequence
    const int grid        = warps_total / BLOCK_WARPS; // 2048 blocks
    biquad_hp_kernel<<<grid, BLOCK_WARPS * 32>>>(x, y, b0, b1, b2, -a1, -a2);
}

// round 9
// speedup vs baseline: 1.1705x; 1.1705x over previous
#include <cuda_runtime.h>
#include <stdint.h>
#include <math.h>

// HighPassFilter: order-2 IIR biquad, 256 sequences of T=65536 float32.
// R9 = R8 with the prefetch OOB bug fixed: at t=0 the distance-2 prefetch
// targets jn=-32, where the sequence-start chunk needs ZERO warm-up input,
// not x[-32..-1] (that unguarded read was also R2's real failure -- identical
// rel_err 2.830794e-03 in both). Guard restored via src_size predication.
// Pipeline: CHUNK=256, WARM=96, cp.async prefetch distance 2, 3-buffer ring.

#define T_LEN   65536
#define CHUNK   256     // samples per lane (validated)
#define WARM    96      // warm-up samples (validated)
#define JT      32      // j-tile width
#define NT      ((CHUNK + WARM) / JT)   // 11 tiles per warp
#define NBUF    3       // SMEM ring depth (prefetch distance 2)
#define BLOCK_WARPS 2
#define ROWSTRIDE 36    // 32 + 4 pad; 16B accesses at 144B stride: conflict-free

#define ROWBYTES  (ROWSTRIDE * 4)       // 144
#define BUFBYTES  (32 * ROWBYTES)       // 4608

__device__ __forceinline__ void cp_async16(uint32_t dst_smem, const float* src, int src_size)
{
    asm volatile("cp.async.cg.shared.global [%0], [%1], 16, %2;\n"
                 :: "r"(dst_smem), "l"(src), "r"(src_size));
}

__global__ __launch_bounds__(BLOCK_WARPS * 32, 1)
void biquad_hp_kernel(const float* __restrict__ x, float* __restrict__ y,
                      float b0, float b1, float b2, float na1, float na2)
{
    // 3-deep ring of transpose tiles per warp
    __shared__ __align__(16) float tile[BLOCK_WARPS][NBUF][32][ROWSTRIDE];

    const int w    = threadIdx.x >> 5;
    const int lane = threadIdx.x & 31;
    const int g    = lane >> 3;   // chunk subgroup (0..3)
    const int m    = lane & 7;    // float4 slot within 32-sample tile (0..7)

    // 8 warps per sequence, each warp owns 32 contiguous chunks = 8192 samples
    const int gw   = blockIdx.x * BLOCK_WARPS + w;
    const int seq  = gw >> 3;
    const int wseq = gw & 7;

    const long long seqbase = (long long)seq * T_LEN;
    const float* xs = x + seqbase;
    float*       ys = y + seqbase;
    const int warpbase = wseq * (32 * CHUNK);
    const int slotbase = warpbase + g * CHUNK + 4 * m;

    // SMEM byte addresses of this lane's cp.async destination, per ring slot.
    // it-step "it" targets row c = it*4+g, float offset 4m:
    //   byte = it*(4*ROWBYTES) + g*ROWBYTES + 16*m
    uint32_t smem_dst[NBUF];
    {
        uint32_t base;
        asm("{ .reg .u64 t; cvta.to.shared.u64 t, %1; cvt.u32.u64 %0, t; }"
            : "=r"(base) : "l"(&tile[w][0][0][0]));
        const uint32_t off = (uint32_t)g * ROWBYTES + (uint32_t)m * 16;
        #pragma unroll
        for (int b = 0; b < NBUF; ++b)
            smem_dst[b] = base + (uint32_t)b * BUFBYTES + off;
    }
    const uint32_t rowstep = 4 * ROWBYTES;   // 576 bytes per it-step

    float xm1 = 0.f, xm2 = 0.f, ym1 = 0.f, ym2 = 0.f;

    // ---- prologue: prefetch tiles 0 and 1 (separate commit groups)
    #pragma unroll
    for (int pt = 0; pt < 2; ++pt) {
        const int jt = -WARM + pt * JT;
        #pragma unroll
        for (int it = 0; it < 8; ++it) {
            int p = slotbase + it * (4 * CHUNK) + jt;
            cp_async16(smem_dst[pt] + it * rowstep,
                       xs + (p >= 0 ? p : 0), p >= 0 ? 16 : 0);
        }
        asm volatile("cp.async.commit_group;\n");
    }

    #pragma unroll
    for (int t = 0; t < NT; ++t) {
        const int  jt   = -WARM + t * JT;
        const bool emit = (jt >= 0);
        float (*buf)[ROWSTRIDE] = tile[w][t % NBUF];
        float* row = buf[lane];

        // ---- issue tile t+2's cp.async (distance-2 lead). GUARDED: at t=0
        //      jn=-32 and the sequence-start chunk must see ZEROS, not x[-32..-1].
        //      Always commit a group so "all but 2 newest" == "tile t complete".
        if (t + 2 < NT) {
            const int jn = jt + 2 * JT;
            #pragma unroll
            for (int it = 0; it < 8; ++it) {
                int p = slotbase + it * (4 * CHUNK) + jn;
                cp_async16(smem_dst[(t + 2) % NBUF] + it * rowstep,
                           xs + (p >= 0 ? p : 0), p >= 0 ? 16 : 0);
            }
        }
        asm volatile("cp.async.commit_group;\n");
        asm volatile("cp.async.wait_group 2;\n");   // tile t's data landed
        __syncwarp();

        // ---- advance this lane's chunk 32 samples (serial IIR chain)
        #pragma unroll
        for (int jj = 0; jj < JT; jj += 4) {
            float4 xv = *reinterpret_cast<float4*>(&row[jj]);

            float t0 = fmaf(b2, xm2, fmaf(b1, xm1, b0 * xv.x));
            float y0 = fmaf(na2, ym2, fmaf(na1, ym1, t0));
            float t1 = fmaf(b2, xm1, fmaf(b1, xv.x, b0 * xv.y));
            float y1 = fmaf(na2, ym1, fmaf(na1, y0, t1));
            float t2 = fmaf(b2, xv.x, fmaf(b1, xv.y, b0 * xv.z));
            float y2 = fmaf(na2, y0, fmaf(na1, y1, t2));
            float t3 = fmaf(b2, xv.y, fmaf(b1, xv.z, b0 * xv.w));
            float y3 = fmaf(na2, y1, fmaf(na1, y2, t3));

            xm2 = xv.z; xm1 = xv.w;
            ym2 = y2;   ym1 = y3;

            if (emit)
                *reinterpret_cast<float4*>(&row[jj]) =
                    make_float4(y0, y1, y2, y3);
        }
        __syncwarp();

        // ---- coalesced store of computed tile (in-place transposed SMEM)
        if (emit) {
            #pragma unroll
            for (int it = 0; it < 8; ++it) {
                int c = it * 4 + g;
                int p = slotbase + it * (4 * CHUNK) + jt;
                *reinterpret_cast<float4*>(ys + p) =
                    *reinterpret_cast<const float4*>(&buf[c][4 * m]);
            }
        }
        __syncwarp();
    }
}

extern "C" void kernel_launch(void* const* d_in, const int* in_sizes, int n_in,
                              void* d_out, int out_size)
{
    const float* x = (const float*)d_in[0];
    float*       y = (float*)d_out;

    const int total = in_sizes[0];
    const int nseq  = total / T_LEN;          // 256 for the given shapes

    const double w0    = 2.0 * M_PI * (700.0 / 16000.0);
    const double cw    = cos(w0);
    const double sw    = sin(w0);
    const double q     = 0.70710678;
    const double alpha = sw / (2.0 * q);
    const double a0    = 1.0 + alpha;

    const float b0 = (float)(((1.0 + cw) / 2.0) / a0);
    const float b1 = (float)((-(1.0 + cw)) / a0);
    const float b2 = b0;
    const float a1 = (float)((-2.0 * cw) / a0);
    const float a2 = (float)((1.0 - alpha) / a0);

    const int warps_total = nseq * 8;                  // 8 warps per sequence
    const int grid        = warps_total / BLOCK_WARPS; // 1024 blocks
    biquad_hp_kernel<<<grid, BLOCK_WARPS * 32>>>(x, y, b0, b1, b2, -a1, -a2);
}